// round 1
// baseline (speedup 1.0000x reference)
#include <cuda_runtime.h>
#include <math.h>

#define Bsz  4
#define Cdim 512
#define HCd  64
#define Npix 4096

// ---- scratch (static device allocations; no cudaMalloc allowed) ----
__device__ float g_scale[4];                 // 1/sigma for Wf, Wg, Wh, Wv
__device__ float g_f[Bsz * Npix * HCd];      // [B][N][HC]
__device__ float g_g[Bsz * Npix * HCd];
__device__ float g_h[Bsz * Npix * HCd];
__device__ float g_o[Bsz * Npix * HCd];

// ============================================================================
// 1) sigma = ||W (W^T u)|| / ||W^T u||   ->  store 1/sigma
//    One block per matrix. Deterministic tree reductions (graph replays must
//    be bit-stable enough; avoid float atomics).
// ============================================================================
__global__ void sigma_kernel(const float* __restrict__ Wf, const float* __restrict__ uf,
                             const float* __restrict__ Wg, const float* __restrict__ ug,
                             const float* __restrict__ Wh, const float* __restrict__ uh,
                             const float* __restrict__ Wv, const float* __restrict__ uv) {
    __shared__ float su[512];
    __shared__ float sv[512];
    __shared__ float sred[512];
    __shared__ float s_nv2;

    int idx = blockIdx.x;
    const float* W; const float* u; int R, Cn;
    if (idx == 0)      { W = Wf; u = uf; R = 64;  Cn = 512; }
    else if (idx == 1) { W = Wg; u = ug; R = 64;  Cn = 512; }
    else if (idx == 2) { W = Wh; u = uh; R = 64;  Cn = 512; }
    else               { W = Wv; u = uv; R = 512; Cn = 64;  }

    int t = threadIdx.x;
    if (t < R) su[t] = u[t];
    __syncthreads();

    // v = W^T u  (unnormalized), nv2 = ||v||^2
    float nv2p = 0.f;
    for (int c = t; c < Cn; c += 512) {
        float acc = 0.f;
        for (int r = 0; r < R; r++) acc += W[r * Cn + c] * su[r];
        sv[c] = acc;
        nv2p += acc * acc;
    }
    sred[t] = nv2p;
    __syncthreads();
    for (int s = 256; s > 0; s >>= 1) { if (t < s) sred[t] += sred[t + s]; __syncthreads(); }
    if (t == 0) s_nv2 = sred[0];
    __syncthreads();

    // w = W v, nw2 = ||w||^2
    float nw2p = 0.f;
    for (int r = t; r < R; r += 512) {
        float acc = 0.f;
        for (int c = 0; c < Cn; c++) acc += W[r * Cn + c] * sv[c];
        nw2p += acc * acc;
    }
    sred[t] = nw2p;
    __syncthreads();
    for (int s = 256; s > 0; s >>= 1) { if (t < s) sred[t] += sred[t + s]; __syncthreads(); }
    if (t == 0) g_scale[idx] = sqrtf(s_nv2 / sred[0]);   // 1/sigma = ||v||/||Wv||
}

// ============================================================================
// 2) Fused projections: f/g/h[b][n][k] = sum_c (W*scale)[k][c] x[b][c][n] + b[k]
//    Block: 64 pixels x 64 HC, 256 threads, 4x4 register tile per thread.
//    tx (0..15) -> hc group (coalesced stores), ty (0..15) -> pixel group.
// ============================================================================
__global__ void __launch_bounds__(256) fgh_kernel(
    const float* __restrict__ x,
    const float* __restrict__ Wf, const float* __restrict__ bf,
    const float* __restrict__ Wg, const float* __restrict__ bg,
    const float* __restrict__ Wh, const float* __restrict__ bh) {
    __shared__ float xs[32][68];    // xs[cc][n]
    __shared__ float wfs[32][68];   // wfs[cc][hc] (transposed, scale folded)
    __shared__ float wgs[32][68];
    __shared__ float whs[32][68];

    int b = blockIdx.y;
    int n0 = blockIdx.x * 64;
    int t = threadIdx.x;
    int tx = t & 15, ty = t >> 4;

    float sf = g_scale[0], sg = g_scale[1], sh = g_scale[2];
    float af[4][4] = {{0}}, ag[4][4] = {{0}}, ah[4][4] = {{0}};

    for (int c0 = 0; c0 < Cdim; c0 += 32) {
        __syncthreads();
        #pragma unroll
        for (int i = 0; i < 8; i++) {               // 32x64 x tile
            int id = t + i * 256;
            int cc = id >> 6, nn = id & 63;
            xs[cc][nn] = x[((size_t)b * Cdim + c0 + cc) * Npix + n0 + nn];
        }
        #pragma unroll
        for (int i = 0; i < 8; i++) {               // 64x32 weight tiles (transposed)
            int id = t + i * 256;
            int hc = id >> 5, cc = id & 31;
            wfs[cc][hc] = Wf[hc * Cdim + c0 + cc] * sf;
            wgs[cc][hc] = Wg[hc * Cdim + c0 + cc] * sg;
            whs[cc][hc] = Wh[hc * Cdim + c0 + cc] * sh;
        }
        __syncthreads();
        #pragma unroll 4
        for (int cc = 0; cc < 32; cc++) {
            float4 wf4 = *(const float4*)&wfs[cc][tx * 4];
            float4 wg4 = *(const float4*)&wgs[cc][tx * 4];
            float4 wh4 = *(const float4*)&whs[cc][tx * 4];
            float xn[4];
            #pragma unroll
            for (int ni = 0; ni < 4; ni++) xn[ni] = xs[cc][ty * 4 + ni];
            #pragma unroll
            for (int ni = 0; ni < 4; ni++) {
                af[ni][0] += xn[ni] * wf4.x; af[ni][1] += xn[ni] * wf4.y;
                af[ni][2] += xn[ni] * wf4.z; af[ni][3] += xn[ni] * wf4.w;
                ag[ni][0] += xn[ni] * wg4.x; ag[ni][1] += xn[ni] * wg4.y;
                ag[ni][2] += xn[ni] * wg4.z; ag[ni][3] += xn[ni] * wg4.w;
                ah[ni][0] += xn[ni] * wh4.x; ah[ni][1] += xn[ni] * wh4.y;
                ah[ni][2] += xn[ni] * wh4.z; ah[ni][3] += xn[ni] * wh4.w;
            }
        }
    }

    float bf4[4], bg4[4], bh4[4];
    #pragma unroll
    for (int hi = 0; hi < 4; hi++) {
        bf4[hi] = bf[tx * 4 + hi];
        bg4[hi] = bg[tx * 4 + hi];
        bh4[hi] = bh[tx * 4 + hi];
    }
    #pragma unroll
    for (int ni = 0; ni < 4; ni++) {
        int n = n0 + ty * 4 + ni;
        size_t base = ((size_t)b * Npix + n) * HCd + tx * 4;
        float4 vf = make_float4(af[ni][0] + bf4[0], af[ni][1] + bf4[1],
                                af[ni][2] + bf4[2], af[ni][3] + bf4[3]);
        float4 vg = make_float4(ag[ni][0] + bg4[0], ag[ni][1] + bg4[1],
                                ag[ni][2] + bg4[2], ag[ni][3] + bg4[3]);
        float4 vh = make_float4(ah[ni][0] + bh4[0], ah[ni][1] + bh4[1],
                                ah[ni][2] + bh4[2], ah[ni][3] + bh4[3]);
        *(float4*)&g_f[base] = vf;
        *(float4*)&g_g[base] = vg;
        *(float4*)&g_h[base] = vh;
    }
}

// ============================================================================
// 3) Flash attention. Q = f, K = g, V = h, all [B][N][64].
//    Block: 64 queries; loop over 64-key tiles. 256 threads.
//    ty (0..15) -> query group of 4 (row stats via 16-lane shuffles),
//    tx (0..15) -> key group (S phase) / dim group (O phase).
//    P tile reuses the K smem buffer.
// ============================================================================
__global__ void __launch_bounds__(256) attn_kernel() {
    extern __shared__ float smem[];
    float* qs = smem;               // [64][68] d-major: qs[d*68 + q]
    float* ks = smem + 64 * 68;     // [64][68] d-major: ks[d*68 + k]; later P[q*68 + k]
    float* vs = smem + 2 * 64 * 68; // [64][68] k-major: vs[k*68 + d]

    int b = blockIdx.y;
    int q0 = blockIdx.x * 64;
    int t = threadIdx.x;
    int tx = t & 15, ty = t >> 4;

    #pragma unroll
    for (int i = 0; i < 16; i++) {  // load Q transposed
        int id = t + i * 256;
        int q = id >> 6, d = id & 63;
        qs[d * 68 + q] = g_f[((size_t)b * Npix + q0 + q) * HCd + d];
    }

    float o[4][4] = {{0}};
    float rmax[4], rsum[4];
    #pragma unroll
    for (int qi = 0; qi < 4; qi++) { rmax[qi] = -1e30f; rsum[qi] = 0.f; }

    for (int m0 = 0; m0 < Npix; m0 += 64) {
        __syncthreads();  // previous P/V consumption done
        #pragma unroll
        for (int i = 0; i < 16; i++) {
            int id = t + i * 256;
            int k = id >> 6, d = id & 63;
            ks[d * 68 + k] = g_g[((size_t)b * Npix + m0 + k) * HCd + d];
            vs[k * 68 + d] = g_h[((size_t)b * Npix + m0 + k) * HCd + d];
        }
        __syncthreads();

        // S = Q K^T (4x4 tile per thread)
        float s[4][4] = {{0}};
        #pragma unroll 8
        for (int d = 0; d < 64; d++) {
            float4 qv = *(const float4*)&qs[d * 68 + ty * 4];
            float4 kv = *(const float4*)&ks[d * 68 + tx * 4];
            float qa[4] = {qv.x, qv.y, qv.z, qv.w};
            #pragma unroll
            for (int qi = 0; qi < 4; qi++) {
                s[qi][0] += qa[qi] * kv.x; s[qi][1] += qa[qi] * kv.y;
                s[qi][2] += qa[qi] * kv.z; s[qi][3] += qa[qi] * kv.w;
            }
        }

        // online softmax per query row (16 lanes own a row)
        #pragma unroll
        for (int qi = 0; qi < 4; qi++) {
            float m = fmaxf(fmaxf(s[qi][0], s[qi][1]), fmaxf(s[qi][2], s[qi][3]));
            #pragma unroll
            for (int off = 8; off > 0; off >>= 1)
                m = fmaxf(m, __shfl_xor_sync(0xffffffffu, m, off));
            float nm = fmaxf(rmax[qi], m);
            float corr = __expf(rmax[qi] - nm);
            float ts = 0.f;
            #pragma unroll
            for (int ki = 0; ki < 4; ki++) {
                s[qi][ki] = __expf(s[qi][ki] - nm);
                ts += s[qi][ki];
            }
            #pragma unroll
            for (int off = 8; off > 0; off >>= 1)
                ts += __shfl_xor_sync(0xffffffffu, ts, off);
            rsum[qi] = rsum[qi] * corr + ts;
            rmax[qi] = nm;
            #pragma unroll
            for (int di = 0; di < 4; di++) o[qi][di] *= corr;
        }

        __syncthreads();  // everyone done reading ks (K) before overwrite with P
        #pragma unroll
        for (int qi = 0; qi < 4; qi++)
            *(float4*)&ks[(ty * 4 + qi) * 68 + tx * 4] =
                make_float4(s[qi][0], s[qi][1], s[qi][2], s[qi][3]);
        __syncthreads();

        // O += P V  (tx now indexes the 4-dim group)
        #pragma unroll 8
        for (int k = 0; k < 64; k++) {
            float4 vv = *(const float4*)&vs[k * 68 + tx * 4];
            #pragma unroll
            for (int qi = 0; qi < 4; qi++) {
                float p = ks[(ty * 4 + qi) * 68 + k];
                o[qi][0] += p * vv.x; o[qi][1] += p * vv.y;
                o[qi][2] += p * vv.z; o[qi][3] += p * vv.w;
            }
        }
    }

    #pragma unroll
    for (int qi = 0; qi < 4; qi++) {
        float inv = 1.f / rsum[qi];
        int n = q0 + ty * 4 + qi;
        *(float4*)&g_o[((size_t)b * Npix + n) * HCd + tx * 4] =
            make_float4(o[qi][0] * inv, o[qi][1] * inv, o[qi][2] * inv, o[qi][3] * inv);
    }
}

// ============================================================================
// 4) out[b][c][n] = gamma * (sum_k (Wv*scale)[c][k] o[b][n][k] + bv[c]) + x[b][c][n]
//    Block: 64 n x 64 c, full k=64.  tx -> n group (coalesced), ty -> c group.
// ============================================================================
__global__ void __launch_bounds__(256) outproj_kernel(
    const float* __restrict__ x, const float* __restrict__ Wv,
    const float* __restrict__ bv, const float* __restrict__ gamma,
    float* __restrict__ out) {
    __shared__ float ot[64 * 68];   // ot[k*68 + n] (transposed o tile)
    __shared__ float wvs[64 * 68];  // wvs[c*68 + k] (scale folded)

    int b = blockIdx.z;
    int c0 = blockIdx.y * 64;
    int n0 = blockIdx.x * 64;
    int t = threadIdx.x;
    int tx = t & 15, ty = t >> 4;
    float sv = g_scale[3];

    #pragma unroll
    for (int i = 0; i < 16; i++) {
        int id = t + i * 256;
        int r = id >> 6, q = id & 63;
        ot[q * 68 + r] = g_o[((size_t)b * Npix + n0 + r) * HCd + q];  // r=n, q=k
        wvs[r * 68 + q] = Wv[(size_t)(c0 + r) * HCd + q] * sv;        // r=c, q=k
    }
    __syncthreads();

    float acc[4][4] = {{0}};
    #pragma unroll 8
    for (int k = 0; k < 64; k++) {
        float4 ov = *(const float4*)&ot[k * 68 + tx * 4];
        #pragma unroll
        for (int ci = 0; ci < 4; ci++) {
            float w = wvs[(ty * 4 + ci) * 68 + k];
            acc[ci][0] += w * ov.x; acc[ci][1] += w * ov.y;
            acc[ci][2] += w * ov.z; acc[ci][3] += w * ov.w;
        }
    }

    float gm = gamma[0];
    #pragma unroll
    for (int ci = 0; ci < 4; ci++) {
        int c = c0 + ty * 4 + ci;
        float bias = bv[c];
        size_t gi = ((size_t)b * Cdim + c) * Npix + n0 + tx * 4;
        float4 xin = *(const float4*)&x[gi];
        float4 r;
        r.x = gm * (acc[ci][0] + bias) + xin.x;
        r.y = gm * (acc[ci][1] + bias) + xin.y;
        r.z = gm * (acc[ci][2] + bias) + xin.z;
        r.w = gm * (acc[ci][3] + bias) + xin.w;
        *(float4*)&out[gi] = r;
    }
}

// ============================================================================
// launcher
// ============================================================================
extern "C" void kernel_launch(void* const* d_in, const int* in_sizes, int n_in,
                              void* d_out, int out_size) {
    (void)in_sizes; (void)n_in; (void)out_size;
    const float* x  = (const float*)d_in[0];
    const float* Wf = (const float*)d_in[1];
    const float* bf = (const float*)d_in[2];
    const float* Wg = (const float*)d_in[3];
    const float* bg = (const float*)d_in[4];
    const float* Wh = (const float*)d_in[5];
    const float* bh = (const float*)d_in[6];
    const float* Wv = (const float*)d_in[7];
    const float* bv = (const float*)d_in[8];
    const float* uf = (const float*)d_in[9];
    const float* ug = (const float*)d_in[10];
    const float* uh = (const float*)d_in[11];
    const float* uv = (const float*)d_in[12];
    const float* gamma = (const float*)d_in[13];
    float* out = (float*)d_out;

    static int attn_smem_set = 0;
    const int attn_smem = 3 * 64 * 68 * (int)sizeof(float);  // 52224 B
    if (!attn_smem_set) {
        cudaFuncSetAttribute(attn_kernel, cudaFuncAttributeMaxDynamicSharedMemorySize, attn_smem);
        attn_smem_set = 1;
    }

    sigma_kernel<<<4, 512>>>(Wf, uf, Wg, ug, Wh, uh, Wv, uv);
    fgh_kernel<<<dim3(Npix / 64, Bsz), 256>>>(x, Wf, bf, Wg, bg, Wh, bh);
    attn_kernel<<<dim3(Npix / 64, Bsz), 256, attn_smem>>>();
    outproj_kernel<<<dim3(Npix / 64, Cdim / 64, Bsz), 256>>>(x, Wv, bv, gamma, out);
}

// round 2
// speedup vs baseline: 1.9784x; 1.9784x over previous
#include <cuda_runtime.h>
#include <math.h>
#include <stdint.h>

#define Bsz  4
#define Cdim 512
#define HCd  64
#define Npix 4096

// ---- scratch (static device allocations; no cudaMalloc allowed) ----
__device__ float g_scale[4];                 // 1/sigma for Wf, Wg, Wh, Wv
__device__ float g_f[Bsz * Npix * HCd];      // [B][N][HC]
__device__ float g_g[Bsz * Npix * HCd];
__device__ float g_h[Bsz * Npix * HCd];
__device__ float g_o[Bsz * Npix * HCd];

// ---- tf32 helpers ----
__device__ __forceinline__ uint32_t f2tf(float x) {
    uint32_t y; asm("cvt.rna.tf32.f32 %0, %1;" : "=r"(y) : "f"(x)); return y;
}
__device__ __forceinline__ float f2tff(float x) { return __uint_as_float(f2tf(x)); }

__device__ __forceinline__ void mma8(float* c, const uint32_t* a, const uint32_t* b) {
    asm volatile(
        "mma.sync.aligned.m16n8k8.row.col.f32.tf32.tf32.f32 "
        "{%0,%1,%2,%3}, {%4,%5,%6,%7}, {%8,%9}, {%0,%1,%2,%3};"
        : "+f"(c[0]), "+f"(c[1]), "+f"(c[2]), "+f"(c[3])
        : "r"(a[0]), "r"(a[1]), "r"(a[2]), "r"(a[3]), "r"(b[0]), "r"(b[1]));
}

// ============================================================================
// 1) sigma = ||W (W^T u)|| / ||W^T u||   ->  store 1/sigma
// ============================================================================
__global__ void sigma_kernel(const float* __restrict__ Wf, const float* __restrict__ uf,
                             const float* __restrict__ Wg, const float* __restrict__ ug,
                             const float* __restrict__ Wh, const float* __restrict__ uh,
                             const float* __restrict__ Wv, const float* __restrict__ uv) {
    __shared__ float su[512];
    __shared__ float sv[512];
    __shared__ float sred[512];
    __shared__ float s_nv2;

    int idx = blockIdx.x;
    const float* W; const float* u; int R, Cn;
    if (idx == 0)      { W = Wf; u = uf; R = 64;  Cn = 512; }
    else if (idx == 1) { W = Wg; u = ug; R = 64;  Cn = 512; }
    else if (idx == 2) { W = Wh; u = uh; R = 64;  Cn = 512; }
    else               { W = Wv; u = uv; R = 512; Cn = 64;  }

    int t = threadIdx.x;
    if (t < R) su[t] = u[t];
    __syncthreads();

    float nv2p = 0.f;
    for (int c = t; c < Cn; c += 512) {
        float acc = 0.f;
        for (int r = 0; r < R; r++) acc += W[r * Cn + c] * su[r];
        sv[c] = acc;
        nv2p += acc * acc;
    }
    sred[t] = nv2p;
    __syncthreads();
    for (int s = 256; s > 0; s >>= 1) { if (t < s) sred[t] += sred[t + s]; __syncthreads(); }
    if (t == 0) s_nv2 = sred[0];
    __syncthreads();

    float nw2p = 0.f;
    for (int r = t; r < R; r += 512) {
        float acc = 0.f;
        for (int c = 0; c < Cn; c++) acc += W[r * Cn + c] * sv[c];
        nw2p += acc * acc;
    }
    sred[t] = nw2p;
    __syncthreads();
    for (int s = 256; s > 0; s >>= 1) { if (t < s) sred[t] += sred[t + s]; __syncthreads(); }
    if (t == 0) g_scale[idx] = sqrtf(s_nv2 / sred[0]);   // 1/sigma
}

// ============================================================================
// 2) Fused projections f/g/h  (fp32, unchanged this round)
// ============================================================================
__global__ void __launch_bounds__(256) fgh_kernel(
    const float* __restrict__ x,
    const float* __restrict__ Wf, const float* __restrict__ bf,
    const float* __restrict__ Wg, const float* __restrict__ bg,
    const float* __restrict__ Wh, const float* __restrict__ bh) {
    __shared__ float xs[32][68];
    __shared__ float wfs[32][68];
    __shared__ float wgs[32][68];
    __shared__ float whs[32][68];

    int b = blockIdx.y;
    int n0 = blockIdx.x * 64;
    int t = threadIdx.x;
    int tx = t & 15, ty = t >> 4;

    float sf = g_scale[0], sg = g_scale[1], sh = g_scale[2];
    float af[4][4] = {{0}}, ag[4][4] = {{0}}, ah[4][4] = {{0}};

    for (int c0 = 0; c0 < Cdim; c0 += 32) {
        __syncthreads();
        #pragma unroll
        for (int i = 0; i < 8; i++) {
            int id = t + i * 256;
            int cc = id >> 6, nn = id & 63;
            xs[cc][nn] = x[((size_t)b * Cdim + c0 + cc) * Npix + n0 + nn];
        }
        #pragma unroll
        for (int i = 0; i < 8; i++) {
            int id = t + i * 256;
            int hc = id >> 5, cc = id & 31;
            wfs[cc][hc] = Wf[hc * Cdim + c0 + cc] * sf;
            wgs[cc][hc] = Wg[hc * Cdim + c0 + cc] * sg;
            whs[cc][hc] = Wh[hc * Cdim + c0 + cc] * sh;
        }
        __syncthreads();
        #pragma unroll 4
        for (int cc = 0; cc < 32; cc++) {
            float4 wf4 = *(const float4*)&wfs[cc][tx * 4];
            float4 wg4 = *(const float4*)&wgs[cc][tx * 4];
            float4 wh4 = *(const float4*)&whs[cc][tx * 4];
            float xn[4];
            #pragma unroll
            for (int ni = 0; ni < 4; ni++) xn[ni] = xs[cc][ty * 4 + ni];
            #pragma unroll
            for (int ni = 0; ni < 4; ni++) {
                af[ni][0] += xn[ni] * wf4.x; af[ni][1] += xn[ni] * wf4.y;
                af[ni][2] += xn[ni] * wf4.z; af[ni][3] += xn[ni] * wf4.w;
                ag[ni][0] += xn[ni] * wg4.x; ag[ni][1] += xn[ni] * wg4.y;
                ag[ni][2] += xn[ni] * wg4.z; ag[ni][3] += xn[ni] * wg4.w;
                ah[ni][0] += xn[ni] * wh4.x; ah[ni][1] += xn[ni] * wh4.y;
                ah[ni][2] += xn[ni] * wh4.z; ah[ni][3] += xn[ni] * wh4.w;
            }
        }
    }

    float bf4[4], bg4[4], bh4[4];
    #pragma unroll
    for (int hi = 0; hi < 4; hi++) {
        bf4[hi] = bf[tx * 4 + hi];
        bg4[hi] = bg[tx * 4 + hi];
        bh4[hi] = bh[tx * 4 + hi];
    }
    #pragma unroll
    for (int ni = 0; ni < 4; ni++) {
        int n = n0 + ty * 4 + ni;
        size_t base = ((size_t)b * Npix + n) * HCd + tx * 4;
        *(float4*)&g_f[base] = make_float4(af[ni][0] + bf4[0], af[ni][1] + bf4[1],
                                           af[ni][2] + bf4[2], af[ni][3] + bf4[3]);
        *(float4*)&g_g[base] = make_float4(ag[ni][0] + bg4[0], ag[ni][1] + bg4[1],
                                           ag[ni][2] + bg4[2], ag[ni][3] + bg4[3]);
        *(float4*)&g_h[base] = make_float4(ah[ni][0] + bh4[0], ah[ni][1] + bh4[1],
                                           ah[ni][2] + bh4[2], ah[ni][3] + bh4[3]);
    }
}

// ============================================================================
// 3) Flash attention with tf32 mma.sync (m16n8k8).
//    Block: 128 queries (8 warps x 16 rows), key tiles of 64. 256 threads.
//    smem tiles hold tf32-rounded values; P round-trips through smem within
//    each warp's own rows (no cross-warp hazard).
// ============================================================================
#define QT 128
#define KT 64

__global__ void __launch_bounds__(256, 1) attn_mma_kernel() {
    extern __shared__ float smem[];
    float* qs = smem;                 // [128][68] row-major (q, d)
    float* ks = qs + QT * 68;         // [64][68]  row-major (k, d)
    float* vs = ks + KT * 68;         // [64][72]  row-major (k, d), pad 72
    float* ps = vs + KT * 72;         // [128][68] row-major (q, k)

    int b = blockIdx.y;
    int q0g = blockIdx.x * QT;
    int tid = threadIdx.x;
    int warp = tid >> 5, lane = tid & 31;
    int gr = lane >> 2, tg = lane & 3;      // groupID, threadID_in_group
    int qr = warp * 16;                     // warp's local query-row base

    // load Q (tf32-rounded)
    #pragma unroll
    for (int i = 0; i < 8; i++) {
        int id = tid + i * 256;
        int row = id >> 4, c4 = (id & 15) * 4;
        float4 v = *(const float4*)&g_f[((size_t)b * Npix + q0g + row) * HCd + c4];
        float* d = &qs[row * 68 + c4];
        d[0] = f2tff(v.x); d[1] = f2tff(v.y); d[2] = f2tff(v.z); d[3] = f2tff(v.w);
    }

    float o[8][4];
    #pragma unroll
    for (int dt = 0; dt < 8; dt++) { o[dt][0] = o[dt][1] = o[dt][2] = o[dt][3] = 0.f; }
    float rmax0 = -1e30f, rmax1 = -1e30f, rsum0 = 0.f, rsum1 = 0.f;

    for (int m0 = 0; m0 < Npix; m0 += KT) {
        __syncthreads();   // prev iter's ks/vs reads done
        #pragma unroll
        for (int i = 0; i < 4; i++) {
            int id = tid + i * 256;
            int row = id >> 4, c4 = (id & 15) * 4;
            size_t gb = ((size_t)b * Npix + m0 + row) * HCd + c4;
            float4 kv = *(const float4*)&g_g[gb];
            float4 vv = *(const float4*)&g_h[gb];
            float* kd = &ks[row * 68 + c4];
            kd[0] = f2tff(kv.x); kd[1] = f2tff(kv.y); kd[2] = f2tff(kv.z); kd[3] = f2tff(kv.w);
            float* vd = &vs[row * 72 + c4];
            vd[0] = f2tff(vv.x); vd[1] = f2tff(vv.y); vd[2] = f2tff(vv.z); vd[3] = f2tff(vv.w);
        }
        __syncthreads();

        // ---- S = Q K^T ----
        uint32_t a[8][4];
        #pragma unroll
        for (int kt = 0; kt < 8; kt++) {
            int c = kt * 8 + tg;
            a[kt][0] = __float_as_uint(qs[(qr + gr) * 68 + c]);
            a[kt][1] = __float_as_uint(qs[(qr + gr + 8) * 68 + c]);
            a[kt][2] = __float_as_uint(qs[(qr + gr) * 68 + c + 4]);
            a[kt][3] = __float_as_uint(qs[(qr + gr + 8) * 68 + c + 4]);
        }
        float s[8][4];
        #pragma unroll
        for (int nt = 0; nt < 8; nt++) { s[nt][0] = s[nt][1] = s[nt][2] = s[nt][3] = 0.f; }
        #pragma unroll
        for (int kt = 0; kt < 8; kt++) {
            #pragma unroll
            for (int nt = 0; nt < 8; nt++) {
                uint32_t bb[2];
                int n = nt * 8 + gr, c = kt * 8 + tg;
                bb[0] = __float_as_uint(ks[n * 68 + c]);
                bb[1] = __float_as_uint(ks[n * 68 + c + 4]);
                mma8(s[nt], a[kt], bb);
            }
        }

        // ---- online softmax (2 rows per thread: gr and gr+8) ----
        float tm0 = -1e30f, tm1 = -1e30f;
        #pragma unroll
        for (int nt = 0; nt < 8; nt++) {
            tm0 = fmaxf(tm0, fmaxf(s[nt][0], s[nt][1]));
            tm1 = fmaxf(tm1, fmaxf(s[nt][2], s[nt][3]));
        }
        tm0 = fmaxf(tm0, __shfl_xor_sync(0xffffffffu, tm0, 1));
        tm0 = fmaxf(tm0, __shfl_xor_sync(0xffffffffu, tm0, 2));
        tm1 = fmaxf(tm1, __shfl_xor_sync(0xffffffffu, tm1, 1));
        tm1 = fmaxf(tm1, __shfl_xor_sync(0xffffffffu, tm1, 2));
        float nm0 = fmaxf(rmax0, tm0), nm1 = fmaxf(rmax1, tm1);
        float corr0 = __expf(rmax0 - nm0), corr1 = __expf(rmax1 - nm1);
        float ts0 = 0.f, ts1 = 0.f;
        #pragma unroll
        for (int nt = 0; nt < 8; nt++) {
            s[nt][0] = __expf(s[nt][0] - nm0);
            s[nt][1] = __expf(s[nt][1] - nm0);
            s[nt][2] = __expf(s[nt][2] - nm1);
            s[nt][3] = __expf(s[nt][3] - nm1);
            ts0 += s[nt][0] + s[nt][1];
            ts1 += s[nt][2] + s[nt][3];
        }
        ts0 += __shfl_xor_sync(0xffffffffu, ts0, 1);
        ts0 += __shfl_xor_sync(0xffffffffu, ts0, 2);
        ts1 += __shfl_xor_sync(0xffffffffu, ts1, 1);
        ts1 += __shfl_xor_sync(0xffffffffu, ts1, 2);
        rsum0 = rsum0 * corr0 + ts0; rmax0 = nm0;
        rsum1 = rsum1 * corr1 + ts1; rmax1 = nm1;
        #pragma unroll
        for (int dt = 0; dt < 8; dt++) {
            o[dt][0] *= corr0; o[dt][1] *= corr0;
            o[dt][2] *= corr1; o[dt][3] *= corr1;
        }

        // ---- write P (own rows only), reload as A frags ----
        #pragma unroll
        for (int nt = 0; nt < 8; nt++) {
            *(float2*)&ps[(qr + gr) * 68 + nt * 8 + 2 * tg] =
                make_float2(f2tff(s[nt][0]), f2tff(s[nt][1]));
            *(float2*)&ps[(qr + gr + 8) * 68 + nt * 8 + 2 * tg] =
                make_float2(f2tff(s[nt][2]), f2tff(s[nt][3]));
        }
        __syncwarp();
        uint32_t pa[8][4];
        #pragma unroll
        for (int kt = 0; kt < 8; kt++) {
            int c = kt * 8 + tg;
            pa[kt][0] = __float_as_uint(ps[(qr + gr) * 68 + c]);
            pa[kt][1] = __float_as_uint(ps[(qr + gr + 8) * 68 + c]);
            pa[kt][2] = __float_as_uint(ps[(qr + gr) * 68 + c + 4]);
            pa[kt][3] = __float_as_uint(ps[(qr + gr + 8) * 68 + c + 4]);
        }

        // ---- O += P V ----
        #pragma unroll
        for (int kt = 0; kt < 8; kt++) {
            #pragma unroll
            for (int dt = 0; dt < 8; dt++) {
                uint32_t bb[2];
                bb[0] = __float_as_uint(vs[(kt * 8 + tg) * 72 + dt * 8 + gr]);
                bb[1] = __float_as_uint(vs[(kt * 8 + tg + 4) * 72 + dt * 8 + gr]);
                mma8(o[dt], pa[kt], bb);
            }
        }
    }

    // epilogue: normalize + store [B][N][64]
    float inv0 = 1.f / rsum0, inv1 = 1.f / rsum1;
    #pragma unroll
    for (int dt = 0; dt < 8; dt++) {
        size_t r0 = ((size_t)b * Npix + q0g + qr + gr) * HCd + dt * 8 + 2 * tg;
        *(float2*)&g_o[r0] = make_float2(o[dt][0] * inv0, o[dt][1] * inv0);
        size_t r1 = ((size_t)b * Npix + q0g + qr + gr + 8) * HCd + dt * 8 + 2 * tg;
        *(float2*)&g_o[r1] = make_float2(o[dt][2] * inv1, o[dt][3] * inv1);
    }
}

// ============================================================================
// 4) out = gamma * (Wv_sn @ o + bv) + x   (fp32, unchanged this round)
// ============================================================================
__global__ void __launch_bounds__(256) outproj_kernel(
    const float* __restrict__ x, const float* __restrict__ Wv,
    const float* __restrict__ bv, const float* __restrict__ gamma,
    float* __restrict__ out) {
    __shared__ float ot[64 * 68];
    __shared__ float wvs[64 * 68];

    int b = blockIdx.z;
    int c0 = blockIdx.y * 64;
    int n0 = blockIdx.x * 64;
    int t = threadIdx.x;
    int tx = t & 15, ty = t >> 4;
    float sv = g_scale[3];

    #pragma unroll
    for (int i = 0; i < 16; i++) {
        int id = t + i * 256;
        int r = id >> 6, q = id & 63;
        ot[q * 68 + r] = g_o[((size_t)b * Npix + n0 + r) * HCd + q];
        wvs[r * 68 + q] = Wv[(size_t)(c0 + r) * HCd + q] * sv;
    }
    __syncthreads();

    float acc[4][4] = {{0}};
    #pragma unroll 8
    for (int k = 0; k < 64; k++) {
        float4 ov = *(const float4*)&ot[k * 68 + tx * 4];
        #pragma unroll
        for (int ci = 0; ci < 4; ci++) {
            float w = wvs[(ty * 4 + ci) * 68 + k];
            acc[ci][0] += w * ov.x; acc[ci][1] += w * ov.y;
            acc[ci][2] += w * ov.z; acc[ci][3] += w * ov.w;
        }
    }

    float gm = gamma[0];
    #pragma unroll
    for (int ci = 0; ci < 4; ci++) {
        int c = c0 + ty * 4 + ci;
        float bias = bv[c];
        size_t gi = ((size_t)b * Cdim + c) * Npix + n0 + tx * 4;
        float4 xin = *(const float4*)&x[gi];
        float4 r;
        r.x = gm * (acc[ci][0] + bias) + xin.x;
        r.y = gm * (acc[ci][1] + bias) + xin.y;
        r.z = gm * (acc[ci][2] + bias) + xin.z;
        r.w = gm * (acc[ci][3] + bias) + xin.w;
        *(float4*)&out[gi] = r;
    }
}

// ============================================================================
// launcher
// ============================================================================
extern "C" void kernel_launch(void* const* d_in, const int* in_sizes, int n_in,
                              void* d_out, int out_size) {
    (void)in_sizes; (void)n_in; (void)out_size;
    const float* x  = (const float*)d_in[0];
    const float* Wf = (const float*)d_in[1];
    const float* bf = (const float*)d_in[2];
    const float* Wg = (const float*)d_in[3];
    const float* bg = (const float*)d_in[4];
    const float* Wh = (const float*)d_in[5];
    const float* bh = (const float*)d_in[6];
    const float* Wv = (const float*)d_in[7];
    const float* bv = (const float*)d_in[8];
    const float* uf = (const float*)d_in[9];
    const float* ug = (const float*)d_in[10];
    const float* uh = (const float*)d_in[11];
    const float* uv = (const float*)d_in[12];
    const float* gamma = (const float*)d_in[13];
    float* out = (float*)d_out;

    static int attrs_set = 0;
    const int attn_smem = (QT * 68 + KT * 68 + KT * 72 + QT * 68) * (int)sizeof(float); // 105472
    if (!attrs_set) {
        cudaFuncSetAttribute(attn_mma_kernel, cudaFuncAttributeMaxDynamicSharedMemorySize, attn_smem);
        attrs_set = 1;
    }

    sigma_kernel<<<4, 512>>>(Wf, uf, Wg, ug, Wh, uh, Wv, uv);
    fgh_kernel<<<dim3(Npix / 64, Bsz), 256>>>(x, Wf, bf, Wg, bg, Wh, bh);
    attn_mma_kernel<<<dim3(Npix / QT, Bsz), 256, attn_smem>>>();
    outproj_kernel<<<dim3(Npix / 64, Cdim / 64, Bsz), 256>>>(x, Wv, bv, gamma, out);
}

// round 3
// speedup vs baseline: 2.1668x; 1.0952x over previous
#include <cuda_runtime.h>
#include <math.h>
#include <stdint.h>

#define Bsz  4
#define Cdim 512
#define HCd  64
#define Npix 4096

// ---- scratch (static device allocations; no cudaMalloc allowed) ----
__device__ float g_scale[4];                 // 1/sigma for Wf, Wg, Wh, Wv
__device__ float g_f[Bsz * Npix * HCd];      // [B][N][HC]
__device__ float g_g[Bsz * Npix * HCd];
__device__ float g_h[Bsz * Npix * HCd];
__device__ float g_o[Bsz * Npix * HCd];

// ---- mma helper: tf32 m16n8k8 (raw fp32 bits in; HW truncates mantissa) ----
__device__ __forceinline__ void mma8(float* c, const uint32_t* a, const uint32_t* b) {
    asm volatile(
        "mma.sync.aligned.m16n8k8.row.col.f32.tf32.tf32.f32 "
        "{%0,%1,%2,%3}, {%4,%5,%6,%7}, {%8,%9}, {%0,%1,%2,%3};"
        : "+f"(c[0]), "+f"(c[1]), "+f"(c[2]), "+f"(c[3])
        : "r"(a[0]), "r"(a[1]), "r"(a[2]), "r"(a[3]), "r"(b[0]), "r"(b[1]));
}

__device__ __forceinline__ void cp16(void* sdst, const void* gsrc) {
    uint32_t s = (uint32_t)__cvta_generic_to_shared(sdst);
    asm volatile("cp.async.cg.shared.global [%0], [%1], 16;" :: "r"(s), "l"(gsrc));
}

// ============================================================================
// 1) sigma = ||W (W^T u)|| / ||W^T u||   ->  store 1/sigma
// ============================================================================
__global__ void sigma_kernel(const float* __restrict__ Wf, const float* __restrict__ uf,
                             const float* __restrict__ Wg, const float* __restrict__ ug,
                             const float* __restrict__ Wh, const float* __restrict__ uh,
                             const float* __restrict__ Wv, const float* __restrict__ uv) {
    __shared__ float su[512];
    __shared__ float sv[512];
    __shared__ float sred[512];
    __shared__ float s_nv2;

    int idx = blockIdx.x;
    const float* W; const float* u; int R, Cn;
    if (idx == 0)      { W = Wf; u = uf; R = 64;  Cn = 512; }
    else if (idx == 1) { W = Wg; u = ug; R = 64;  Cn = 512; }
    else if (idx == 2) { W = Wh; u = uh; R = 64;  Cn = 512; }
    else               { W = Wv; u = uv; R = 512; Cn = 64;  }

    int t = threadIdx.x;
    if (t < R) su[t] = u[t];
    __syncthreads();

    float nv2p = 0.f;
    for (int c = t; c < Cn; c += 512) {
        float acc = 0.f;
        for (int r = 0; r < R; r++) acc += W[r * Cn + c] * su[r];
        sv[c] = acc;
        nv2p += acc * acc;
    }
    sred[t] = nv2p;
    __syncthreads();
    for (int s = 256; s > 0; s >>= 1) { if (t < s) sred[t] += sred[t + s]; __syncthreads(); }
    if (t == 0) s_nv2 = sred[0];
    __syncthreads();

    float nw2p = 0.f;
    for (int r = t; r < R; r += 512) {
        float acc = 0.f;
        for (int c = 0; c < Cn; c++) acc += W[r * Cn + c] * sv[c];
        nw2p += acc * acc;
    }
    sred[t] = nw2p;
    __syncthreads();
    for (int s = 256; s > 0; s >>= 1) { if (t < s) sred[t] += sred[t + s]; __syncthreads(); }
    if (t == 0) g_scale[idx] = sqrtf(s_nv2 / sred[0]);   // 1/sigma
}

// ============================================================================
// 2) Fused projections f/g/h  (fp32, unchanged)
// ============================================================================
__global__ void __launch_bounds__(256) fgh_kernel(
    const float* __restrict__ x,
    const float* __restrict__ Wf, const float* __restrict__ bf,
    const float* __restrict__ Wg, const float* __restrict__ bg,
    const float* __restrict__ Wh, const float* __restrict__ bh) {
    __shared__ float xs[32][68];
    __shared__ float wfs[32][68];
    __shared__ float wgs[32][68];
    __shared__ float whs[32][68];

    int b = blockIdx.y;
    int n0 = blockIdx.x * 64;
    int t = threadIdx.x;
    int tx = t & 15, ty = t >> 4;

    float sf = g_scale[0], sg = g_scale[1], sh = g_scale[2];
    float af[4][4] = {{0}}, ag[4][4] = {{0}}, ah[4][4] = {{0}};

    for (int c0 = 0; c0 < Cdim; c0 += 32) {
        __syncthreads();
        #pragma unroll
        for (int i = 0; i < 8; i++) {
            int id = t + i * 256;
            int cc = id >> 6, nn = id & 63;
            xs[cc][nn] = x[((size_t)b * Cdim + c0 + cc) * Npix + n0 + nn];
        }
        #pragma unroll
        for (int i = 0; i < 8; i++) {
            int id = t + i * 256;
            int hc = id >> 5, cc = id & 31;
            wfs[cc][hc] = Wf[hc * Cdim + c0 + cc] * sf;
            wgs[cc][hc] = Wg[hc * Cdim + c0 + cc] * sg;
            whs[cc][hc] = Wh[hc * Cdim + c0 + cc] * sh;
        }
        __syncthreads();
        #pragma unroll 4
        for (int cc = 0; cc < 32; cc++) {
            float4 wf4 = *(const float4*)&wfs[cc][tx * 4];
            float4 wg4 = *(const float4*)&wgs[cc][tx * 4];
            float4 wh4 = *(const float4*)&whs[cc][tx * 4];
            float xn[4];
            #pragma unroll
            for (int ni = 0; ni < 4; ni++) xn[ni] = xs[cc][ty * 4 + ni];
            #pragma unroll
            for (int ni = 0; ni < 4; ni++) {
                af[ni][0] += xn[ni] * wf4.x; af[ni][1] += xn[ni] * wf4.y;
                af[ni][2] += xn[ni] * wf4.z; af[ni][3] += xn[ni] * wf4.w;
                ag[ni][0] += xn[ni] * wg4.x; ag[ni][1] += xn[ni] * wg4.y;
                ag[ni][2] += xn[ni] * wg4.z; ag[ni][3] += xn[ni] * wg4.w;
                ah[ni][0] += xn[ni] * wh4.x; ah[ni][1] += xn[ni] * wh4.y;
                ah[ni][2] += xn[ni] * wh4.z; ah[ni][3] += xn[ni] * wh4.w;
            }
        }
    }

    float bf4[4], bg4[4], bh4[4];
    #pragma unroll
    for (int hi = 0; hi < 4; hi++) {
        bf4[hi] = bf[tx * 4 + hi];
        bg4[hi] = bg[tx * 4 + hi];
        bh4[hi] = bh[tx * 4 + hi];
    }
    #pragma unroll
    for (int ni = 0; ni < 4; ni++) {
        int n = n0 + ty * 4 + ni;
        size_t base = ((size_t)b * Npix + n) * HCd + tx * 4;
        *(float4*)&g_f[base] = make_float4(af[ni][0] + bf4[0], af[ni][1] + bf4[1],
                                           af[ni][2] + bf4[2], af[ni][3] + bf4[3]);
        *(float4*)&g_g[base] = make_float4(ag[ni][0] + bg4[0], ag[ni][1] + bg4[1],
                                           ag[ni][2] + bg4[2], ag[ni][3] + bg4[3]);
        *(float4*)&g_h[base] = make_float4(ah[ni][0] + bh4[0], ah[ni][1] + bh4[1],
                                           ah[ni][2] + bh4[2], ah[ni][3] + bh4[3]);
    }
}

// ============================================================================
// 3) Flash attention, tf32 mma + cp.async 3-slot pipelined K/V, 1 barrier/tile.
//    128 queries/block (8 warps x 16 rows), 64-key tiles.
// ============================================================================
#define QT 128
#define KT 64
#define NTILES (Npix / KT)

__global__ void __launch_bounds__(256, 1) attn_mma_kernel() {
    extern __shared__ float smem[];
    float* qs = smem;                   // [128][68]
    float* ksb = qs + QT * 68;          // 3 x [64][68]
    float* vsb = ksb + 3 * KT * 68;     // 3 x [64][72]
    float* ps = vsb + 3 * KT * 72;      // [128][68]

    int b = blockIdx.y;
    int q0g = blockIdx.x * QT;
    int tid = threadIdx.x;
    int warp = tid >> 5, lane = tid & 31;
    int gr = lane >> 2, tg = lane & 3;
    int qr = warp * 16;

    // per-thread prefetch coords (4 float4 per array)
    int prow[4], pc4[4];
    #pragma unroll
    for (int i = 0; i < 4; i++) {
        int id = tid + i * 256;
        prow[i] = id >> 4; pc4[i] = (id & 15) * 4;
    }
    const float* gK = g_g + (size_t)b * Npix * HCd;
    const float* gV = g_h + (size_t)b * Npix * HCd;

    // prologue: prefetch tiles 0 and 1
    #pragma unroll
    for (int st = 0; st < 2; st++) {
        float* kd = ksb + st * KT * 68;
        float* vd = vsb + st * KT * 72;
        #pragma unroll
        for (int i = 0; i < 4; i++) {
            size_t gb = (size_t)(st * KT + prow[i]) * HCd + pc4[i];
            cp16(&kd[prow[i] * 68 + pc4[i]], gK + gb);
            cp16(&vd[prow[i] * 72 + pc4[i]], gV + gb);
        }
        asm volatile("cp.async.commit_group;");
    }

    // load Q tile (raw fp32)
    #pragma unroll
    for (int i = 0; i < 8; i++) {
        int id = tid + i * 256;
        int row = id >> 4, c4 = (id & 15) * 4;
        *(float4*)&qs[row * 68 + c4] =
            *(const float4*)&g_f[((size_t)b * Npix + q0g + row) * HCd + c4];
    }
    __syncthreads();

    // hoisted Q fragments
    uint32_t a[8][4];
    #pragma unroll
    for (int kt = 0; kt < 8; kt++) {
        int c = kt * 8 + tg;
        a[kt][0] = __float_as_uint(qs[(qr + gr) * 68 + c]);
        a[kt][1] = __float_as_uint(qs[(qr + gr + 8) * 68 + c]);
        a[kt][2] = __float_as_uint(qs[(qr + gr) * 68 + c + 4]);
        a[kt][3] = __float_as_uint(qs[(qr + gr + 8) * 68 + c + 4]);
    }

    float o[8][4];
    #pragma unroll
    for (int dt = 0; dt < 8; dt++) { o[dt][0] = o[dt][1] = o[dt][2] = o[dt][3] = 0.f; }
    float rmax0 = -1e30f, rmax1 = -1e30f, rsum0 = 0.f, rsum1 = 0.f;

    int slot = 0;
    for (int t = 0; t < NTILES; t++) {
        // wait for tile t (last iteration has only its own group pending)
        if (t == NTILES - 1) asm volatile("cp.async.wait_group 0;");
        else                 asm volatile("cp.async.wait_group 1;");
        __syncthreads();   // tile t visible to all; all done with slot (t+2)%3

        // prefetch tile t+2 into the slot freed by tile t-1
        if (t + 2 < NTILES) {
            int st = (slot + 2) % 3;
            float* kd = ksb + st * KT * 68;
            float* vd = vsb + st * KT * 72;
            int m0 = (t + 2) * KT;
            #pragma unroll
            for (int i = 0; i < 4; i++) {
                size_t gb = (size_t)(m0 + prow[i]) * HCd + pc4[i];
                cp16(&kd[prow[i] * 68 + pc4[i]], gK + gb);
                cp16(&vd[prow[i] * 72 + pc4[i]], gV + gb);
            }
            asm volatile("cp.async.commit_group;");
        }

        const float* ks = ksb + slot * KT * 68;
        const float* vs = vsb + slot * KT * 72;

        // ---- S = Q K^T ----
        float s[8][4];
        #pragma unroll
        for (int nt = 0; nt < 8; nt++) { s[nt][0] = s[nt][1] = s[nt][2] = s[nt][3] = 0.f; }
        #pragma unroll
        for (int kt = 0; kt < 8; kt++) {
            #pragma unroll
            for (int nt = 0; nt < 8; nt++) {
                uint32_t bb[2];
                int n = nt * 8 + gr, c = kt * 8 + tg;
                bb[0] = __float_as_uint(ks[n * 68 + c]);
                bb[1] = __float_as_uint(ks[n * 68 + c + 4]);
                mma8(s[nt], a[kt], bb);
            }
        }

        // ---- online softmax (rows gr and gr+8) ----
        float tm0 = -1e30f, tm1 = -1e30f;
        #pragma unroll
        for (int nt = 0; nt < 8; nt++) {
            tm0 = fmaxf(tm0, fmaxf(s[nt][0], s[nt][1]));
            tm1 = fmaxf(tm1, fmaxf(s[nt][2], s[nt][3]));
        }
        tm0 = fmaxf(tm0, __shfl_xor_sync(0xffffffffu, tm0, 1));
        tm0 = fmaxf(tm0, __shfl_xor_sync(0xffffffffu, tm0, 2));
        tm1 = fmaxf(tm1, __shfl_xor_sync(0xffffffffu, tm1, 1));
        tm1 = fmaxf(tm1, __shfl_xor_sync(0xffffffffu, tm1, 2));
        float nm0 = fmaxf(rmax0, tm0), nm1 = fmaxf(rmax1, tm1);
        float corr0 = __expf(rmax0 - nm0), corr1 = __expf(rmax1 - nm1);
        float ts0 = 0.f, ts1 = 0.f;
        #pragma unroll
        for (int nt = 0; nt < 8; nt++) {
            s[nt][0] = __expf(s[nt][0] - nm0);
            s[nt][1] = __expf(s[nt][1] - nm0);
            s[nt][2] = __expf(s[nt][2] - nm1);
            s[nt][3] = __expf(s[nt][3] - nm1);
            ts0 += s[nt][0] + s[nt][1];
            ts1 += s[nt][2] + s[nt][3];
        }
        ts0 += __shfl_xor_sync(0xffffffffu, ts0, 1);
        ts0 += __shfl_xor_sync(0xffffffffu, ts0, 2);
        ts1 += __shfl_xor_sync(0xffffffffu, ts1, 1);
        ts1 += __shfl_xor_sync(0xffffffffu, ts1, 2);
        rsum0 = rsum0 * corr0 + ts0; rmax0 = nm0;
        rsum1 = rsum1 * corr1 + ts1; rmax1 = nm1;
        #pragma unroll
        for (int dt = 0; dt < 8; dt++) {
            o[dt][0] *= corr0; o[dt][1] *= corr0;
            o[dt][2] *= corr1; o[dt][3] *= corr1;
        }

        // ---- P -> smem (own warp rows), reload as A frags ----
        #pragma unroll
        for (int nt = 0; nt < 8; nt++) {
            *(float2*)&ps[(qr + gr) * 68 + nt * 8 + 2 * tg] = make_float2(s[nt][0], s[nt][1]);
            *(float2*)&ps[(qr + gr + 8) * 68 + nt * 8 + 2 * tg] = make_float2(s[nt][2], s[nt][3]);
        }
        __syncwarp();
        uint32_t pa[8][4];
        #pragma unroll
        for (int kt = 0; kt < 8; kt++) {
            int c = kt * 8 + tg;
            pa[kt][0] = __float_as_uint(ps[(qr + gr) * 68 + c]);
            pa[kt][1] = __float_as_uint(ps[(qr + gr + 8) * 68 + c]);
            pa[kt][2] = __float_as_uint(ps[(qr + gr) * 68 + c + 4]);
            pa[kt][3] = __float_as_uint(ps[(qr + gr + 8) * 68 + c + 4]);
        }

        // ---- O += P V ----
        #pragma unroll
        for (int kt = 0; kt < 8; kt++) {
            #pragma unroll
            for (int dt = 0; dt < 8; dt++) {
                uint32_t bb[2];
                bb[0] = __float_as_uint(vs[(kt * 8 + tg) * 72 + dt * 8 + gr]);
                bb[1] = __float_as_uint(vs[(kt * 8 + tg + 4) * 72 + dt * 8 + gr]);
                mma8(o[dt], pa[kt], bb);
            }
        }

        slot++; if (slot == 3) slot = 0;
    }

    // epilogue: normalize + store [B][N][64]
    float inv0 = 1.f / rsum0, inv1 = 1.f / rsum1;
    #pragma unroll
    for (int dt = 0; dt < 8; dt++) {
        size_t r0 = ((size_t)b * Npix + q0g + qr + gr) * HCd + dt * 8 + 2 * tg;
        *(float2*)&g_o[r0] = make_float2(o[dt][0] * inv0, o[dt][1] * inv0);
        size_t r1 = ((size_t)b * Npix + q0g + qr + gr + 8) * HCd + dt * 8 + 2 * tg;
        *(float2*)&g_o[r1] = make_float2(o[dt][2] * inv1, o[dt][3] * inv1);
    }
}

// ============================================================================
// 4) out = gamma * (Wv_sn @ o + bv) + x   (fp32, unchanged)
// ============================================================================
__global__ void __launch_bounds__(256) outproj_kernel(
    const float* __restrict__ x, const float* __restrict__ Wv,
    const float* __restrict__ bv, const float* __restrict__ gamma,
    float* __restrict__ out) {
    __shared__ float ot[64 * 68];
    __shared__ float wvs[64 * 68];

    int b = blockIdx.z;
    int c0 = blockIdx.y * 64;
    int n0 = blockIdx.x * 64;
    int t = threadIdx.x;
    int tx = t & 15, ty = t >> 4;
    float sv = g_scale[3];

    #pragma unroll
    for (int i = 0; i < 16; i++) {
        int id = t + i * 256;
        int r = id >> 6, q = id & 63;
        ot[q * 68 + r] = g_o[((size_t)b * Npix + n0 + r) * HCd + q];
        wvs[r * 68 + q] = Wv[(size_t)(c0 + r) * HCd + q] * sv;
    }
    __syncthreads();

    float acc[4][4] = {{0}};
    #pragma unroll 8
    for (int k = 0; k < 64; k++) {
        float4 ov = *(const float4*)&ot[k * 68 + tx * 4];
        #pragma unroll
        for (int ci = 0; ci < 4; ci++) {
            float w = wvs[(ty * 4 + ci) * 68 + k];
            acc[ci][0] += w * ov.x; acc[ci][1] += w * ov.y;
            acc[ci][2] += w * ov.z; acc[ci][3] += w * ov.w;
        }
    }

    float gm = gamma[0];
    #pragma unroll
    for (int ci = 0; ci < 4; ci++) {
        int c = c0 + ty * 4 + ci;
        float bias = bv[c];
        size_t gi = ((size_t)b * Cdim + c) * Npix + n0 + tx * 4;
        float4 xin = *(const float4*)&x[gi];
        float4 r;
        r.x = gm * (acc[ci][0] + bias) + xin.x;
        r.y = gm * (acc[ci][1] + bias) + xin.y;
        r.z = gm * (acc[ci][2] + bias) + xin.z;
        r.w = gm * (acc[ci][3] + bias) + xin.w;
        *(float4*)&out[gi] = r;
    }
}

// ============================================================================
// launcher
// ============================================================================
extern "C" void kernel_launch(void* const* d_in, const int* in_sizes, int n_in,
                              void* d_out, int out_size) {
    (void)in_sizes; (void)n_in; (void)out_size;
    const float* x  = (const float*)d_in[0];
    const float* Wf = (const float*)d_in[1];
    const float* bf = (const float*)d_in[2];
    const float* Wg = (const float*)d_in[3];
    const float* bg = (const float*)d_in[4];
    const float* Wh = (const float*)d_in[5];
    const float* bh = (const float*)d_in[6];
    const float* Wv = (const float*)d_in[7];
    const float* bv = (const float*)d_in[8];
    const float* uf = (const float*)d_in[9];
    const float* ug = (const float*)d_in[10];
    const float* uh = (const float*)d_in[11];
    const float* uv = (const float*)d_in[12];
    const float* gamma = (const float*)d_in[13];
    float* out = (float*)d_out;

    static int attrs_set = 0;
    const int attn_smem =
        (QT * 68 + 3 * KT * 68 + 3 * KT * 72 + QT * 68) * (int)sizeof(float); // 177152
    if (!attrs_set) {
        cudaFuncSetAttribute(attn_mma_kernel, cudaFuncAttributeMaxDynamicSharedMemorySize, attn_smem);
        attrs_set = 1;
    }

    sigma_kernel<<<4, 512>>>(Wf, uf, Wg, ug, Wh, uh, Wv, uv);
    fgh_kernel<<<dim3(Npix / 64, Bsz), 256>>>(x, Wf, bf, Wg, bg, Wh, bh);
    attn_mma_kernel<<<dim3(Npix / QT, Bsz), 256, attn_smem>>>();
    outproj_kernel<<<dim3(Npix / 64, Cdim / 64, Bsz), 256>>>(x, Wv, bv, gamma, out);
}